// round 6
// baseline (speedup 1.0000x reference)
#include <cuda_runtime.h>
#include <cuda_bf16.h>
#include <stdint.h>

// Fixed problem shapes
#define TT 5
#define BB 8
#define HH 128
#define WW 128
#define HW (HH*WW)
#define C1 3
#define C2 64

#define EPS_AMB 2e-4f
#define FIXCAP (1u<<20)

// ---------------- static scratch ----------------
__device__ __align__(16) uint32_t g_s1b[(size_t)TT*BB*C2*HH*4];   // spike bitplanes (5.2 MB)
// W2 packed into mma.m16n8k16 B-fragment layout, bf16 2-split:
// [slab = split*9+tap][ks(4)][ocg(8)][lane(32)][r(2)]
#define WF_SLAB_U32 (4*8*32*2)          // 2048 u32 = 8KB per slab
__device__ __align__(16) uint32_t g_wf[18*WF_SLAB_U32];
__device__ __align__(16) float    g_w2t[9*C2*C2];                 // [tap][ic][oc] fp32 (for fixup)
__device__ uint32_t g_fixcnt;
__device__ uint32_t g_fix[FIXCAP];

// ---------------- K0: pack W2 fragments + transpose + zero counter ----------------
__global__ void k0_pack_w2(const float* __restrict__ W2) {
    int i = blockIdx.x * 256 + threadIdx.x;
    if (i == 0) g_fixcnt = 0;
    if (i < 18*WF_SLAB_U32) {
        int r    = i & 1;
        int lane = (i >> 1) & 31;
        int ocg  = (i >> 6) & 7;
        int ks   = (i >> 9) & 3;
        int rest = i >> 11;            // slab = split*9 + tap
        int tap  = rest % 9;
        int split= rest / 9;

        int k  = ks*16 + (lane & 3)*2 + r*8;
        int oc = ocg*8 + (lane >> 2);

        float w0 = W2[(oc*C2 + k  )*9 + tap];
        float w1 = W2[(oc*C2 + k+1)*9 + tap];
        if (split) {
            w0 = w0 - __bfloat162float(__float2bfloat16(w0));
            w1 = w1 - __bfloat162float(__float2bfloat16(w1));
        }
        uint16_t h0 = __bfloat16_as_ushort(__float2bfloat16(w0));
        uint16_t h1 = __bfloat16_as_ushort(__float2bfloat16(w1));
        g_wf[i] = (uint32_t)h0 | ((uint32_t)h1 << 16);
    }
    if (i < 9*C2*C2) {
        int oc  = i / (C2*9);
        int r   = i % (C2*9);
        int ic  = r / 9;
        int tap = r % 9;
        g_w2t[(tap*C2 + ic)*C2 + oc] = W2[i];
    }
}

// ---------------- K1: conv1 (3->64, 3x3, pad1) + 5-step LIF1, spikes as bitplanes ----------------
__global__ __launch_bounds__(256) void k1_conv1_lif1(
    const float* __restrict__ x,
    const float* __restrict__ W1,
    const float* __restrict__ b1,
    const float* __restrict__ tau1p)
{
    __shared__ __align__(16) float xs[C1][10][36];
    __shared__ __align__(16) float ws[27][C2];
    __shared__ float bs[C2];

    const int tid = threadIdx.x;
    const int tx = blockIdx.x & 3;
    const int ty = blockIdx.x >> 2;
    const int b  = blockIdx.y;

    for (int i = tid; i < C2*27; i += 256) {
        int o = i / 27, r = i % 27;
        int c = r / 9, t9 = r % 9;
        ws[t9*3 + c][o] = W1[i];
    }
    if (tid < C2) bs[tid] = b1[tid];

    for (int i = tid; i < C1*10*34; i += 256) {
        int c = i / 340, r = i % 340, y = r / 34, xc = r % 34;
        int gy = ty*8 - 1 + y, gx = tx*32 - 1 + xc;
        float v = 0.f;
        if ((unsigned)gy < (unsigned)HH && (unsigned)gx < (unsigned)WW)
            v = x[((size_t)b*C1 + c)*HW + gy*WW + gx];
        xs[c][y][xc] = v;
    }
    __syncthreads();

    const int px = tid & 31, py = tid >> 5;

    float acc[C2];
    #pragma unroll
    for (int o = 0; o < C2; ++o) acc[o] = 0.f;

    #pragma unroll
    for (int dy = 0; dy < 3; ++dy)
        #pragma unroll
        for (int dx = 0; dx < 3; ++dx)
            #pragma unroll
            for (int c = 0; c < C1; ++c) {
                float xv = xs[c][py+dy][px+dx];
                const float4* wp = (const float4*)&ws[(dy*3+dx)*3 + c][0];
                #pragma unroll
                for (int q = 0; q < 16; ++q) {
                    float4 w = wp[q];
                    acc[q*4+0] = fmaf(w.x, xv, acc[q*4+0]);
                    acc[q*4+1] = fmaf(w.y, xv, acc[q*4+1]);
                    acc[q*4+2] = fmaf(w.z, xv, acc[q*4+2]);
                    acc[q*4+3] = fmaf(w.w, xv, acc[q*4+3]);
                }
            }

    float tau = tau1p[0];
    tau = fminf(fmaxf(tau, 0.5f), 5.0f);
    const float it = 1.0f / tau;
    const int gy = ty*8 + py;

    #pragma unroll
    for (int o = 0; o < C2; ++o) {
        const float xo = __fadd_rn(acc[o], bs[o]);
        float v = 0.f;
        #pragma unroll
        for (int t = 0; t < TT; ++t) {
            v = __fadd_rn(v, __fmul_rn(it, __fadd_rn(xo, -v)));
            int s = (__fadd_rn(v, -0.1f) >= 0.f);
            v = s ? 0.f : fminf(fmaxf(v, -2.f), 2.f);
            unsigned w = __ballot_sync(0xffffffffu, s);
            if (px == 0)
                g_s1b[(((size_t)t*BB + b)*C2 + o)*HH*4 + (size_t)gy*4 + tx] = w;
        }
    }
}

// ---------------- mma helper ----------------
__device__ __forceinline__ void mma16816(float* c, const uint32_t* a, uint32_t b0, uint32_t b1) {
    asm volatile(
        "mma.sync.aligned.m16n8k16.row.col.f32.bf16.bf16.f32 "
        "{%0,%1,%2,%3}, {%4,%5,%6,%7}, {%8,%9}, {%0,%1,%2,%3};\n"
        : "+f"(c[0]), "+f"(c[1]), "+f"(c[2]), "+f"(c[3])
        : "r"(a[0]), "r"(a[1]), "r"(a[2]), "r"(a[3]), "r"(b0), "r"(b1));
}
__device__ __forceinline__ uint32_t pk2(uint32_t ra, uint32_t rb, int s) {
    return (((ra >> s) & 1u) * 0x3F80u) | (((rb >> s) & 1u) * 0x3F800000u);
}

// ---------------- K2: fused conv2(bf16 HMMA, all weights in smem) + LIF2 + head ----------------
// dynamic smem: wf_all (144KB) + sbuf (4.6KB). grid (64 tiles, 8 batch), block 256.
__global__ __launch_bounds__(256, 1) void k2_fused(
    const float* __restrict__ b2,
    const float* __restrict__ Wh,    // [3][64]
    const float* __restrict__ bh,
    const float* __restrict__ tau2p,
    float* __restrict__ out)
{
    extern __shared__ __align__(16) uint32_t dsm[];
    uint32_t* wf_all = dsm;                       // 18*2048 u32
    uint32_t* sbuf   = dsm + 18*WF_SLAB_U32;      // [ic][18]
    __shared__ float wh_s[3*C2];
    __shared__ float bias_s[C2];

    const int tid  = threadIdx.x;
    const int warp = tid >> 5, lane = tid & 31;
    const int t4 = lane & 3, gid = lane >> 2;
    const int tx = blockIdx.x & 7, ty = blockIdx.x >> 3;
    const int b  = blockIdx.y;

    for (int i = tid; i < 3*C2; i += 256) wh_s[i] = Wh[i];
    if (tid < C2) bias_s[tid] = b2[tid];

    // load ALL weight slabs once (36864 u32 = 9216 uint4)
    {
        const uint4* src = (const uint4*)g_wf;
        uint4* dst = (uint4*)wf_all;
        for (int i = tid; i < 18*WF_SLAB_U32/4; i += 256) dst[i] = src[i];
    }

    float tau = tau2p[0];
    tau = fminf(fmaxf(tau, 0.5f), 5.0f);
    const float it = 1.0f / tau;
    const float bh0 = bh[0], bh1 = bh[1], bh2 = bh[2];

    float v[2][8][4];
    uint32_t slotw[2][8];   // bits (4t+j): hmma spike; bits 24+j: ambiguity flag
    #pragma unroll
    for (int f = 0; f < 2; ++f)
        #pragma unroll
        for (int g = 0; g < 8; ++g) {
            slotw[f][g] = 0u;
            #pragma unroll
            for (int j = 0; j < 4; ++j) v[f][g][j] = 0.f;
        }

    for (int t = 0; t < TT; ++t) {
        __syncthreads();   // sbuf consumers of prev t done; also covers wf_all/wh (t==0)

        {   // build spike bit rows for (t,b): 18-bit windows, bit k = x = tx*16-1+k
            const uint32_t* src = g_s1b + (size_t)(t*BB + b)*C2*HH*4;
            for (int i = tid; i < C2*18; i += 256) {
                int ic = i / 18, y = i % 18;
                int gy = ty*16 - 1 + y;
                uint32_t val = 0;
                if ((unsigned)gy < (unsigned)HH) {
                    int g0 = tx*16 - 1;
                    int w0 = g0 >> 5;
                    int off = g0 & 31;
                    const uint32_t* rowp = src + ((size_t)ic*HH + gy)*4;
                    uint32_t lo = (w0 >= 0) ? rowp[w0] : 0u;
                    uint32_t hi = (w0 + 1 <= 3) ? rowp[w0 + 1] : 0u;
                    val = __funnelshift_r(lo, hi, off);
                }
                sbuf[ic*18 + y] = val;
            }
        }
        __syncthreads();

        float acc[2][8][4];
        #pragma unroll
        for (int f = 0; f < 2; ++f)
            #pragma unroll
            for (int g = 0; g < 8; ++g)
                #pragma unroll
                for (int j = 0; j < 4; ++j) acc[f][g][j] = 0.f;

        for (int st = 0; st < 18; ++st) {
            const int tap = (st >= 9) ? (st - 9) : st;
            const int dy = tap / 3, dx = tap % 3;
            const int s0 = gid + dx, s1 = s0 + 8;
            const int yr0 = 2*warp + dy;
            const uint32_t* wfs = wf_all + st*WF_SLAB_U32;

            #pragma unroll
            for (int ks = 0; ks < 4; ++ks) {
                const int icb = ks*16 + 2*t4;
                uint32_t a0[4], a1[4];
                {
                    uint32_t r0 = sbuf[(icb  )*18 + yr0];
                    uint32_t r1 = sbuf[(icb+1)*18 + yr0];
                    uint32_t r2 = sbuf[(icb+8)*18 + yr0];
                    uint32_t r3 = sbuf[(icb+9)*18 + yr0];
                    a0[0] = pk2(r0, r1, s0); a0[1] = pk2(r0, r1, s1);
                    a0[2] = pk2(r2, r3, s0); a0[3] = pk2(r2, r3, s1);
                }
                {
                    uint32_t r0 = sbuf[(icb  )*18 + yr0 + 1];
                    uint32_t r1 = sbuf[(icb+1)*18 + yr0 + 1];
                    uint32_t r2 = sbuf[(icb+8)*18 + yr0 + 1];
                    uint32_t r3 = sbuf[(icb+9)*18 + yr0 + 1];
                    a1[0] = pk2(r0, r1, s0); a1[1] = pk2(r0, r1, s1);
                    a1[2] = pk2(r2, r3, s0); a1[3] = pk2(r2, r3, s1);
                }
                #pragma unroll
                for (int g = 0; g < 8; ++g) {
                    const uint32_t* bp = wfs + (((ks*8 + g)*32 + lane) << 1);
                    uint32_t b0 = bp[0], b1 = bp[1];
                    mma16816(acc[0][g], a0, b0, b1);
                    mma16816(acc[1][g], a1, b0, b1);
                }
            }
        }

        // LIF2 + head partials, with ambiguity flagging
        float hp[2][2][3];
        #pragma unroll
        for (int f = 0; f < 2; ++f)
            #pragma unroll
            for (int xh = 0; xh < 2; ++xh)
                { hp[f][xh][0] = 0.f; hp[f][xh][1] = 0.f; hp[f][xh][2] = 0.f; }

        #pragma unroll
        for (int f = 0; f < 2; ++f)
            #pragma unroll
            for (int g = 0; g < 8; ++g)
                #pragma unroll
                for (int j = 0; j < 4; ++j) {
                    const int oc = g*8 + 2*t4 + (j & 1);
                    const int xh = j >> 1;
                    float y = __fadd_rn(acc[f][g][j], bias_s[oc]);
                    float vv = __fadd_rn(v[f][g][j], __fmul_rn(it, __fadd_rn(y, -v[f][g][j])));
                    float m = __fadd_rn(vv, -0.1f);
                    int s = (m >= 0.f);
                    if (fabsf(m) < EPS_AMB) slotw[f][g] |= (1u << (24 + j));
                    slotw[f][g] |= ((uint32_t)s << (4*t + j));
                    v[f][g][j] = s ? 0.f : fminf(fmaxf(vv, -2.f), 2.f);
                    if (s) {
                        hp[f][xh][0] = __fadd_rn(hp[f][xh][0], wh_s[oc]);
                        hp[f][xh][1] = __fadd_rn(hp[f][xh][1], wh_s[C2 + oc]);
                        hp[f][xh][2] = __fadd_rn(hp[f][xh][2], wh_s[2*C2 + oc]);
                    }
                }

        #pragma unroll
        for (int f = 0; f < 2; ++f)
            #pragma unroll
            for (int xh = 0; xh < 2; ++xh)
                #pragma unroll
                for (int ch = 0; ch < 3; ++ch) {
                    float val = hp[f][xh][ch];
                    val = __fadd_rn(val, __shfl_xor_sync(0xffffffffu, val, 1));
                    val = __fadd_rn(val, __shfl_xor_sync(0xffffffffu, val, 2));
                    hp[f][xh][ch] = val;
                }

        if (t4 == 0) {
            const int gybase = ty*16 + 2*warp;
            const int gxbase = tx*16 + gid;
            #pragma unroll
            for (int f = 0; f < 2; ++f)
                #pragma unroll
                for (int xh = 0; xh < 2; ++xh) {
                    size_t ob = ((size_t)(t*BB + b)*3)*HW + (size_t)(gybase + f)*WW + gxbase + 8*xh;
                    out[ob]        = __fadd_rn(hp[f][xh][0], bh0);
                    out[ob +  HW]  = __fadd_rn(hp[f][xh][1], bh1);
                    out[ob + 2*HW] = __fadd_rn(hp[f][xh][2], bh2);
                }
        }
    }

    // emit fixup records for ambiguous slots
    #pragma unroll
    for (int f = 0; f < 2; ++f)
        #pragma unroll
        for (int g = 0; g < 8; ++g) {
            uint32_t w = slotw[f][g];
            uint32_t ambm = w >> 24;
            if (ambm) {
                #pragma unroll
                for (int j = 0; j < 4; ++j) {
                    if ((ambm >> j) & 1u) {
                        int oc = g*8 + 2*t4 + (j & 1);
                        int xh = j >> 1;
                        int gy = ty*16 + 2*warp + f;
                        int gx = tx*16 + gid + 8*xh;
                        uint32_t sh5 = 0;
                        #pragma unroll
                        for (int t = 0; t < TT; ++t) sh5 |= ((w >> (4*t + j)) & 1u) << t;
                        uint32_t rec = (uint32_t)(gy*WW + gx) | ((uint32_t)oc << 14)
                                     | ((uint32_t)b << 20) | (sh5 << 23);
                        uint32_t idx = atomicAdd(&g_fixcnt, 1u);
                        if (idx < FIXCAP) g_fix[idx] = rec;
                    }
                }
            }
        }
}

// ---------------- K3: fixup — replay ambiguous elements in exact sequential fp32 order ----------------
__global__ void k3_fixup(const float* __restrict__ b2,
                         const float* __restrict__ Wh,
                         const float* __restrict__ tau2p,
                         float* __restrict__ out)
{
    uint32_t cnt = g_fixcnt;
    if (cnt > FIXCAP) cnt = FIXCAP;

    float tau = tau2p[0];
    tau = fminf(fmaxf(tau, 0.5f), 5.0f);
    const float it = 1.0f / tau;

    for (uint32_t i = blockIdx.x*blockDim.x + threadIdx.x; i < cnt; i += gridDim.x*blockDim.x) {
        uint32_t rec = g_fix[i];
        int pixel = rec & 16383;
        int oc    = (rec >> 14) & 63;
        int b     = (rec >> 20) & 7;
        uint32_t sh = (rec >> 23) & 31;
        int py = pixel >> 7, px = pixel & 127;

        float v = 0.f;
        const float bia = b2[oc];
        for (int t = 0; t < TT; ++t) {
            const uint32_t* base = g_s1b + (size_t)(t*BB + b)*C2*HH*4;
            float acc = 0.f;
            for (int tap = 0; tap < 9; ++tap) {
                int dy = tap / 3, dx = tap % 3;
                int gy = py + dy - 1, gx = px + dx - 1;
                if ((unsigned)gy < (unsigned)HH && (unsigned)gx < (unsigned)WW) {
                    int wi = gx >> 5, off = gx & 31;
                    const float* wp = g_w2t + (size_t)tap*C2*C2 + oc;
                    const uint32_t* bp = base + (size_t)gy*4 + wi;
                    for (int ic = 0; ic < C2; ++ic) {
                        if ((bp[(size_t)ic*HH*4] >> off) & 1u)
                            acc = __fadd_rn(acc, wp[ic*C2]);
                    }
                }
            }
            float y = __fadd_rn(acc, bia);
            float vv = __fadd_rn(v, __fmul_rn(it, __fadd_rn(y, -v)));
            int s = (__fadd_rn(vv, -0.1f) >= 0.f);
            v = s ? 0.f : fminf(fmaxf(vv, -2.f), 2.f);

            int s_h = (sh >> t) & 1;
            if (s != s_h) {
                float d = s ? 1.f : -1.f;
                #pragma unroll
                for (int ch = 0; ch < 3; ++ch)
                    atomicAdd(&out[((size_t)(t*BB + b)*3 + ch)*HW + pixel], d * Wh[ch*C2 + oc]);
            }
        }
    }
}

// ---------------- launch ----------------
extern "C" void kernel_launch(void* const* d_in, const int* in_sizes, int n_in,
                              void* d_out, int out_size)
{
    const float* lr_lab = (const float*)d_in[0];
    const float* W1     = (const float*)d_in[1];
    const float* b1     = (const float*)d_in[2];
    const float* tau1   = (const float*)d_in[3];
    const float* W2     = (const float*)d_in[4];
    const float* b2     = (const float*)d_in[5];
    const float* tau2   = (const float*)d_in[6];
    const float* Wh     = (const float*)d_in[7];
    const float* bh     = (const float*)d_in[8];
    float* out = (float*)d_out;

    const int smem_k2 = (18*WF_SLAB_U32 + C2*18) * 4;   // ~152 KB
    cudaFuncSetAttribute(k2_fused, cudaFuncAttributeMaxDynamicSharedMemorySize, smem_k2);

    k0_pack_w2<<<(18*WF_SLAB_U32 + 255)/256, 256>>>(W2);
    k1_conv1_lif1<<<dim3(64, BB), 256>>>(lr_lab, W1, b1, tau1);
    k2_fused<<<dim3(64, BB), 256, smem_k2>>>(b2, Wh, bh, tau2, out);
    k3_fixup<<<64, 128>>>(b2, Wh, tau2, out);
}